// round 4
// baseline (speedup 1.0000x reference)
#include <cuda_runtime.h>
#include <math.h>

// ---------------------------------------------------------------------------
// TSControllerCoordinateTransform
//   x: (1, 10, T) f32, T = 4,000,000 ; reference_axis: (3,) f32
//   out: (2, 3, T) f32  = [new_basis @ (Xpos - refPos) ; Add]
//
// 3 kernels:
//   K1 stats:    9 moments of rows 0..2 (f32 per-thread partials, f64 reduce)
//   K2 finalize: cov -> f32-rounded -> f64 3x3 eigensolve (max eig) -> basis
//   K3 transform: newX rows + copy of rows 7..9 (grid-stride, float4)
// ---------------------------------------------------------------------------

#define NB_STATS 1024
#define NT_STATS 256

__device__ double g_partials[NB_STATS * 9];
__device__ float  g_params[12];   // basis row-major (9) + refPos (3)

__inline__ __device__ double warp_reduce_d(double v) {
    #pragma unroll
    for (int o = 16; o > 0; o >>= 1)
        v += __shfl_down_sync(0xffffffffu, v, o);
    return v;
}

__global__ __launch_bounds__(NT_STATS)
void stats_kernel(const float* __restrict__ x, int T) {
    const int T4 = T >> 2;
    const float4* r0 = reinterpret_cast<const float4*>(x);
    const float4* r1 = reinterpret_cast<const float4*>(x + T);
    const float4* r2 = reinterpret_cast<const float4*>(x + 2 * T);

    float sx = 0.f, sy = 0.f, sz = 0.f;
    float sxx = 0.f, sxy = 0.f, sxz = 0.f, syy = 0.f, syz = 0.f, szz = 0.f;

    const int stride = gridDim.x * blockDim.x;
    for (int i = blockIdx.x * blockDim.x + threadIdx.x; i < T4; i += stride) {
        float4 a = r0[i], b = r1[i], c = r2[i];
        #define ACC(ax, bx, cx)                                          \
            sx += (ax); sy += (bx); sz += (cx);                          \
            sxx = fmaf((ax), (ax), sxx); sxy = fmaf((ax), (bx), sxy);    \
            sxz = fmaf((ax), (cx), sxz); syy = fmaf((bx), (bx), syy);    \
            syz = fmaf((bx), (cx), syz); szz = fmaf((cx), (cx), szz);
        ACC(a.x, b.x, c.x) ACC(a.y, b.y, c.y)
        ACC(a.z, b.z, c.z) ACC(a.w, b.w, c.w)
        #undef ACC
    }

    double d[9] = {(double)sx, (double)sy, (double)sz,
                   (double)sxx, (double)sxy, (double)sxz,
                   (double)syy, (double)syz, (double)szz};

    __shared__ double s[(NT_STATS / 32) * 9];
    const int lane = threadIdx.x & 31, warp = threadIdx.x >> 5;
    #pragma unroll
    for (int q = 0; q < 9; q++) {
        double v = warp_reduce_d(d[q]);
        if (lane == 0) s[warp * 9 + q] = v;
    }
    __syncthreads();
    if (threadIdx.x < 9) {
        double t = 0.0;
        #pragma unroll
        for (int w = 0; w < NT_STATS / 32; w++) t += s[w * 9 + threadIdx.x];
        g_partials[blockIdx.x * 9 + threadIdx.x] = t;
    }
}

__global__ __launch_bounds__(NB_STATS)
void finalize_kernel(const float* __restrict__ x,
                     const float* __restrict__ ref_axis, int T) {
    __shared__ double s[(NB_STATS / 32) * 9];
    const int tid = threadIdx.x, lane = tid & 31, warp = tid >> 5;

    double d[9];
    #pragma unroll
    for (int q = 0; q < 9; q++) d[q] = g_partials[tid * 9 + q];
    #pragma unroll
    for (int q = 0; q < 9; q++) {
        double v = warp_reduce_d(d[q]);
        if (lane == 0) s[warp * 9 + q] = v;
    }
    __syncthreads();
    if (tid != 0) return;

    double S[9];
    #pragma unroll
    for (int q = 0; q < 9; q++) {
        double t = 0.0;
        for (int w = 0; w < NB_STATS / 32; w++) t += s[w * 9 + q];
        S[q] = t;
    }

    const double n = (double)T;
    const double inv = 1.0 / (n - 1.0);
    const double mx = S[0] / n, my = S[1] / n, mz = S[2] / n;
    // Round cov to f32 — jnp's eigh input is the f32 cov matrix.
    double c00 = (double)(float)((S[3] - S[0] * mx) * inv);
    double c01 = (double)(float)((S[4] - S[0] * my) * inv);
    double c02 = (double)(float)((S[5] - S[0] * mz) * inv);
    double c11 = (double)(float)((S[6] - S[1] * my) * inv);
    double c12 = (double)(float)((S[7] - S[1] * mz) * inv);
    double c22 = (double)(float)((S[8] - S[2] * mz) * inv);

    // --- largest eigenvalue (analytic, double) ---
    double vx, vy, vz;
    const double p1 = c01 * c01 + c02 * c02 + c12 * c12;
    if (p1 < 1e-300) {
        vx = 1.0; vy = 0.0; vz = 0.0;
        if (c11 >= c00 && c11 >= c22) { vx = 0.0; vy = 1.0; }
        else if (c22 >= c00 && c22 >= c11) { vx = 0.0; vz = 1.0; }
    } else {
        const double q = (c00 + c11 + c22) / 3.0;
        const double p2 = (c00 - q) * (c00 - q) + (c11 - q) * (c11 - q) +
                          (c22 - q) * (c22 - q) + 2.0 * p1;
        const double p = sqrt(p2 / 6.0);
        const double ip = 1.0 / p;
        const double b00 = (c00 - q) * ip, b11 = (c11 - q) * ip, b22 = (c22 - q) * ip;
        const double b01 = c01 * ip, b02 = c02 * ip, b12 = c12 * ip;
        double r = 0.5 * (b00 * (b11 * b22 - b12 * b12)
                        - b01 * (b01 * b22 - b12 * b02)
                        + b02 * (b01 * b12 - b11 * b02));
        r = fmin(1.0, fmax(-1.0, r));
        const double phi = acos(r) / 3.0;
        const double lmax = q + 2.0 * p * cos(phi);

        // eigenvector: largest cross product of rows of (A - lmax I)
        const double m00 = c00 - lmax, m11 = c11 - lmax, m22 = c22 - lmax;
        double u0x = c01 * c12 - c02 * m11;   // r0 x r1
        double u0y = c02 * c01 - m00 * c12;
        double u0z = m00 * m11 - c01 * c01;
        double u1x = c01 * m22 - c02 * c12;   // r0 x r2
        double u1y = c02 * c02 - m00 * m22;
        double u1z = m00 * c12 - c01 * c02;
        double u2x = m11 * m22 - c12 * c12;   // r1 x r2
        double u2y = c12 * c02 - c01 * m22;
        double u2z = c01 * c12 - m11 * c02;
        double n0 = u0x * u0x + u0y * u0y + u0z * u0z;
        double n1 = u1x * u1x + u1y * u1y + u1z * u1z;
        double n2 = u2x * u2x + u2y * u2y + u2z * u2z;
        if (n0 >= n1 && n0 >= n2)      { vx = u0x; vy = u0y; vz = u0z; }
        else if (n1 >= n2)             { vx = u1x; vy = u1y; vz = u1z; }
        else                           { vx = u2x; vy = u2y; vz = u2z; }
        const double nrm = rsqrt(vx * vx + vy * vy + vz * vz);
        vx *= nrm; vy *= nrm; vz *= nrm;
    }

    // --- sign fix vs quaternion Z-forward (quat unnormalized, as in ref) ---
    const double qx = (double)x[3 * (size_t)T];
    const double qy = (double)x[4 * (size_t)T];
    const double qz = (double)x[5 * (size_t)T];
    const double qw = (double)x[6 * (size_t)T];
    const double zfx = 2.0 * (qx * qz + qw * qy);
    const double zfy = 2.0 * (qy * qz - qw * qx);
    const double zfz = 1.0 - 2.0 * (qx * qx + qy * qy);
    if (zfx * vx + zfy * vy + zfz * vz < 0.0) { vx = -vx; vy = -vy; vz = -vz; }

    // --- basis in f32 (matching jnp's f32 crosses) ---
    const float pzx = (float)vx, pzy = (float)vy, pzz = (float)vz;
    const float ax = ref_axis[0], ay = ref_axis[1], az = ref_axis[2];
    const float nrx = ay * pzz - az * pzy;    // new_right = cross(ref, pz)
    const float nry = az * pzx - ax * pzz;
    const float nrz = ax * pzy - ay * pzx;
    const float nfx = nry * az - nrz * ay;    // new_fwd = cross(new_right, new_up)
    const float nfy = nrz * ax - nrx * az;
    const float nfz = nrx * ay - nry * ax;

    g_params[0] = nrx; g_params[1] = nry; g_params[2] = nrz;
    g_params[3] = ax;  g_params[4] = ay;  g_params[5] = az;
    g_params[6] = nfx; g_params[7] = nfy; g_params[8] = nfz;
    g_params[9]  = x[0];
    g_params[10] = x[(size_t)T];
    g_params[11] = x[2 * (size_t)T];
}

// Grid-stride; each iteration front-batches 6 LDG.128 (high MLP_p1).
__global__ __launch_bounds__(256)
void transform_kernel(const float* __restrict__ x, float* __restrict__ out, int T) {
    const int T4 = T >> 2;

    const float b00 = g_params[0], b01 = g_params[1], b02 = g_params[2];
    const float b10 = g_params[3], b11 = g_params[4], b12 = g_params[5];
    const float b20 = g_params[6], b21 = g_params[7], b22 = g_params[8];
    const float rx  = g_params[9], ry  = g_params[10], rz = g_params[11];

    const float4* X0 = reinterpret_cast<const float4*>(x);
    const float4* X1 = reinterpret_cast<const float4*>(x + T);
    const float4* X2 = reinterpret_cast<const float4*>(x + 2 * T);
    const float4* A0 = reinterpret_cast<const float4*>(x + 7 * (size_t)T);
    const float4* A1 = reinterpret_cast<const float4*>(x + 8 * (size_t)T);
    const float4* A2 = reinterpret_cast<const float4*>(x + 9 * (size_t)T);

    float4* O0 = reinterpret_cast<float4*>(out);
    float4* O1 = reinterpret_cast<float4*>(out + T);
    float4* O2 = reinterpret_cast<float4*>(out + 2 * T);
    float4* O3 = reinterpret_cast<float4*>(out + 3 * (size_t)T);
    float4* O4 = reinterpret_cast<float4*>(out + 4 * (size_t)T);
    float4* O5 = reinterpret_cast<float4*>(out + 5 * (size_t)T);

    const int stride = gridDim.x * blockDim.x;
    for (int i = blockIdx.x * blockDim.x + threadIdx.x; i < T4; i += stride) {
        float4 v0 = X0[i], v1 = X1[i], v2 = X2[i];
        float4 a0 = A0[i], a1 = A1[i], a2 = A2[i];
        float4 o0, o1, o2;
        #define LANE(L)                                                        \
            {                                                                  \
                const float dx = v0.L - rx, dy = v1.L - ry, dz = v2.L - rz;    \
                o0.L = fmaf(b00, dx, fmaf(b01, dy, b02 * dz));                 \
                o1.L = fmaf(b10, dx, fmaf(b11, dy, b12 * dz));                 \
                o2.L = fmaf(b20, dx, fmaf(b21, dy, b22 * dz));                 \
            }
        LANE(x) LANE(y) LANE(z) LANE(w)
        #undef LANE
        O0[i] = o0; O1[i] = o1; O2[i] = o2;
        O3[i] = a0; O4[i] = a1; O5[i] = a2;
    }
}

extern "C" void kernel_launch(void* const* d_in, const int* in_sizes, int n_in,
                              void* d_out, int out_size) {
    // Defensive: identify x (large) vs reference_axis (3 elements)
    int xi = 0, ri = 1;
    if (n_in >= 2 && in_sizes[0] == 3) { xi = 1; ri = 0; }
    const float* x  = (const float*)d_in[xi];
    const float* ra = (const float*)d_in[ri];
    const int T = in_sizes[xi] / 10;

    stats_kernel<<<NB_STATS, NT_STATS>>>(x, T);
    finalize_kernel<<<1, NB_STATS>>>(x, ra, T);

    const int T4 = T >> 2;
    // ~2 iterations per thread, capped to keep full waves on 148 SMs.
    int blocks = (T4 + 2 * 256 - 1) / (2 * 256);
    if (blocks < 1) blocks = 1;
    transform_kernel<<<blocks, 256>>>(x, (float*)d_out, T);
}

// round 7
// speedup vs baseline: 1.0204x; 1.0204x over previous
#include <cuda_runtime.h>
#include <math.h>

// ---------------------------------------------------------------------------
// TSControllerCoordinateTransform
//   x: (1, 10, T) f32, T = 4,000,000 ; reference_axis: (3,) f32
//   out: (2, 3, T) f32  = [new_basis @ (Xpos - refPos) ; Add]
//
// R4/R5/R6: batch loads across unrolled grid-stride steps (MLP_p1 3->12 in
// stats, 6->12 in transform) to convert both kernels from latency-bound
// (measured R3: DRAM 15.7%, issue 10.8%, regs=32) to bandwidth-bound.
// ---------------------------------------------------------------------------

#define NB_STATS 1024
#define NT_STATS 256

__device__ double g_partials[NB_STATS * 9];
__device__ float  g_params[12];   // basis row-major (9) + refPos (3)

__inline__ __device__ double warp_reduce_d(double v) {
    #pragma unroll
    for (int o = 16; o > 0; o >>= 1)
        v += __shfl_down_sync(0xffffffffu, v, o);
    return v;
}

__global__ __launch_bounds__(NT_STATS)
void stats_kernel(const float* __restrict__ x, int T) {
    const int T4 = T >> 2;
    const float4* __restrict__ r0 = reinterpret_cast<const float4*>(x);
    const float4* __restrict__ r1 = reinterpret_cast<const float4*>(x + T);
    const float4* __restrict__ r2 = reinterpret_cast<const float4*>(x + 2 * T);

    float sx = 0.f, sy = 0.f, sz = 0.f;
    float sxx = 0.f, sxy = 0.f, sxz = 0.f, syy = 0.f, syz = 0.f, szz = 0.f;

    const int stride = gridDim.x * blockDim.x;
    const float4 z4 = make_float4(0.f, 0.f, 0.f, 0.f);

    for (int base = blockIdx.x * blockDim.x + threadIdx.x; base < T4;
         base += 4 * stride) {
        // Front-batch all 12 loads (predicated) before any consumption.
        float4 a[4], b[4], c[4];
        #pragma unroll
        for (int u = 0; u < 4; u++) {
            const int idx = base + u * stride;
            const bool p = idx < T4;
            a[u] = p ? r0[idx] : z4;
            b[u] = p ? r1[idx] : z4;
            c[u] = p ? r2[idx] : z4;
        }
        #pragma unroll
        for (int u = 0; u < 4; u++) {
            #define ACC(ax, bx, cx)                                          \
                sx += (ax); sy += (bx); sz += (cx);                          \
                sxx = fmaf((ax), (ax), sxx); sxy = fmaf((ax), (bx), sxy);    \
                sxz = fmaf((ax), (cx), sxz); syy = fmaf((bx), (bx), syy);    \
                syz = fmaf((bx), (cx), syz); szz = fmaf((cx), (cx), szz);
            ACC(a[u].x, b[u].x, c[u].x) ACC(a[u].y, b[u].y, c[u].y)
            ACC(a[u].z, b[u].z, c[u].z) ACC(a[u].w, b[u].w, c[u].w)
            #undef ACC
        }
    }

    double d[9] = {(double)sx, (double)sy, (double)sz,
                   (double)sxx, (double)sxy, (double)sxz,
                   (double)syy, (double)syz, (double)szz};

    __shared__ double s[(NT_STATS / 32) * 9];
    const int lane = threadIdx.x & 31, warp = threadIdx.x >> 5;
    #pragma unroll
    for (int q = 0; q < 9; q++) {
        double v = warp_reduce_d(d[q]);
        if (lane == 0) s[warp * 9 + q] = v;
    }
    __syncthreads();
    if (threadIdx.x < 9) {
        double t = 0.0;
        #pragma unroll
        for (int w = 0; w < NT_STATS / 32; w++) t += s[w * 9 + threadIdx.x];
        g_partials[blockIdx.x * 9 + threadIdx.x] = t;
    }
}

__global__ __launch_bounds__(NB_STATS)
void finalize_kernel(const float* __restrict__ x,
                     const float* __restrict__ ref_axis, int T) {
    __shared__ double s[(NB_STATS / 32) * 9];
    const int tid = threadIdx.x, lane = tid & 31, warp = tid >> 5;

    double d[9];
    #pragma unroll
    for (int q = 0; q < 9; q++) d[q] = g_partials[tid * 9 + q];
    #pragma unroll
    for (int q = 0; q < 9; q++) {
        double v = warp_reduce_d(d[q]);
        if (lane == 0) s[warp * 9 + q] = v;
    }
    __syncthreads();
    if (tid != 0) return;

    double S[9];
    #pragma unroll
    for (int q = 0; q < 9; q++) {
        double t = 0.0;
        for (int w = 0; w < NB_STATS / 32; w++) t += s[w * 9 + q];
        S[q] = t;
    }

    const double n = (double)T;
    const double inv = 1.0 / (n - 1.0);
    const double mx = S[0] / n, my = S[1] / n, mz = S[2] / n;
    // Round cov to f32 — jnp's eigh input is the f32 cov matrix.
    double c00 = (double)(float)((S[3] - S[0] * mx) * inv);
    double c01 = (double)(float)((S[4] - S[0] * my) * inv);
    double c02 = (double)(float)((S[5] - S[0] * mz) * inv);
    double c11 = (double)(float)((S[6] - S[1] * my) * inv);
    double c12 = (double)(float)((S[7] - S[1] * mz) * inv);
    double c22 = (double)(float)((S[8] - S[2] * mz) * inv);

    // --- largest eigenvalue (analytic, double) ---
    double vx, vy, vz;
    const double p1 = c01 * c01 + c02 * c02 + c12 * c12;
    if (p1 < 1e-300) {
        vx = 1.0; vy = 0.0; vz = 0.0;
        if (c11 >= c00 && c11 >= c22) { vx = 0.0; vy = 1.0; }
        else if (c22 >= c00 && c22 >= c11) { vx = 0.0; vz = 1.0; }
    } else {
        const double q = (c00 + c11 + c22) / 3.0;
        const double p2 = (c00 - q) * (c00 - q) + (c11 - q) * (c11 - q) +
                          (c22 - q) * (c22 - q) + 2.0 * p1;
        const double p = sqrt(p2 / 6.0);
        const double ip = 1.0 / p;
        const double b00 = (c00 - q) * ip, b11 = (c11 - q) * ip, b22 = (c22 - q) * ip;
        const double b01 = c01 * ip, b02 = c02 * ip, b12 = c12 * ip;
        double r = 0.5 * (b00 * (b11 * b22 - b12 * b12)
                        - b01 * (b01 * b22 - b12 * b02)
                        + b02 * (b01 * b12 - b11 * b02));
        r = fmin(1.0, fmax(-1.0, r));
        const double phi = acos(r) / 3.0;
        const double lmax = q + 2.0 * p * cos(phi);

        // eigenvector: largest cross product of rows of (A - lmax I)
        const double m00 = c00 - lmax, m11 = c11 - lmax, m22 = c22 - lmax;
        double u0x = c01 * c12 - c02 * m11;   // r0 x r1
        double u0y = c02 * c01 - m00 * c12;
        double u0z = m00 * m11 - c01 * c01;
        double u1x = c01 * m22 - c02 * c12;   // r0 x r2
        double u1y = c02 * c02 - m00 * m22;
        double u1z = m00 * c12 - c01 * c02;
        double u2x = m11 * m22 - c12 * c12;   // r1 x r2
        double u2y = c12 * c02 - c01 * m22;
        double u2z = c01 * c12 - m11 * c02;
        double n0 = u0x * u0x + u0y * u0y + u0z * u0z;
        double n1 = u1x * u1x + u1y * u1y + u1z * u1z;
        double n2 = u2x * u2x + u2y * u2y + u2z * u2z;
        if (n0 >= n1 && n0 >= n2)      { vx = u0x; vy = u0y; vz = u0z; }
        else if (n1 >= n2)             { vx = u1x; vy = u1y; vz = u1z; }
        else                           { vx = u2x; vy = u2y; vz = u2z; }
        const double nrm = rsqrt(vx * vx + vy * vy + vz * vz);
        vx *= nrm; vy *= nrm; vz *= nrm;
    }

    // --- sign fix vs quaternion Z-forward (quat unnormalized, as in ref) ---
    const double qx = (double)x[3 * (size_t)T];
    const double qy = (double)x[4 * (size_t)T];
    const double qz = (double)x[5 * (size_t)T];
    const double qw = (double)x[6 * (size_t)T];
    const double zfx = 2.0 * (qx * qz + qw * qy);
    const double zfy = 2.0 * (qy * qz - qw * qx);
    const double zfz = 1.0 - 2.0 * (qx * qx + qy * qy);
    if (zfx * vx + zfy * vy + zfz * vz < 0.0) { vx = -vx; vy = -vy; vz = -vz; }

    // --- basis in f32 (matching jnp's f32 crosses) ---
    const float pzx = (float)vx, pzy = (float)vy, pzz = (float)vz;
    const float ax = ref_axis[0], ay = ref_axis[1], az = ref_axis[2];
    const float nrx = ay * pzz - az * pzy;    // new_right = cross(ref, pz)
    const float nry = az * pzx - ax * pzz;
    const float nrz = ax * pzy - ay * pzx;
    const float nfx = nry * az - nrz * ay;    // new_fwd = cross(new_right, new_up)
    const float nfy = nrz * ax - nrx * az;
    const float nfz = nrx * ay - nry * ax;

    g_params[0] = nrx; g_params[1] = nry; g_params[2] = nrz;
    g_params[3] = ax;  g_params[4] = ay;  g_params[5] = az;
    g_params[6] = nfx; g_params[7] = nfy; g_params[8] = nfz;
    g_params[9]  = x[0];
    g_params[10] = x[(size_t)T];
    g_params[11] = x[2 * (size_t)T];
}

// 2 grid-stride steps per pass, all 12 loads front-batched.
__global__ __launch_bounds__(256)
void transform_kernel(const float* __restrict__ x, float* __restrict__ out, int T) {
    const int T4 = T >> 2;

    const float b00 = g_params[0], b01 = g_params[1], b02 = g_params[2];
    const float b10 = g_params[3], b11 = g_params[4], b12 = g_params[5];
    const float b20 = g_params[6], b21 = g_params[7], b22 = g_params[8];
    const float rx  = g_params[9], ry  = g_params[10], rz = g_params[11];

    const float4* __restrict__ X0 = reinterpret_cast<const float4*>(x);
    const float4* __restrict__ X1 = reinterpret_cast<const float4*>(x + T);
    const float4* __restrict__ X2 = reinterpret_cast<const float4*>(x + 2 * T);
    const float4* __restrict__ A0 = reinterpret_cast<const float4*>(x + 7 * (size_t)T);
    const float4* __restrict__ A1 = reinterpret_cast<const float4*>(x + 8 * (size_t)T);
    const float4* __restrict__ A2 = reinterpret_cast<const float4*>(x + 9 * (size_t)T);

    float4* __restrict__ O0 = reinterpret_cast<float4*>(out);
    float4* __restrict__ O1 = reinterpret_cast<float4*>(out + T);
    float4* __restrict__ O2 = reinterpret_cast<float4*>(out + 2 * T);
    float4* __restrict__ O3 = reinterpret_cast<float4*>(out + 3 * (size_t)T);
    float4* __restrict__ O4 = reinterpret_cast<float4*>(out + 4 * (size_t)T);
    float4* __restrict__ O5 = reinterpret_cast<float4*>(out + 5 * (size_t)T);

    const int stride = gridDim.x * blockDim.x;
    const float4 z4 = make_float4(0.f, 0.f, 0.f, 0.f);

    for (int base = blockIdx.x * blockDim.x + threadIdx.x; base < T4;
         base += 2 * stride) {
        const int i0 = base, i1 = base + stride;
        const bool p1 = i1 < T4;

        // Front-batch all loads.
        float4 v0a = X0[i0], v1a = X1[i0], v2a = X2[i0];
        float4 a0a = A0[i0], a1a = A1[i0], a2a = A2[i0];
        float4 v0b = p1 ? X0[i1] : z4, v1b = p1 ? X1[i1] : z4, v2b = p1 ? X2[i1] : z4;
        float4 a0b = p1 ? A0[i1] : z4, a1b = p1 ? A1[i1] : z4, a2b = p1 ? A2[i1] : z4;

        float4 o0a, o1a, o2a, o0b, o1b, o2b;
        #define LANE(v0, v1, v2, o0, o1, o2, L)                                \
            {                                                                  \
                const float dx = v0.L - rx, dy = v1.L - ry, dz = v2.L - rz;    \
                o0.L = fmaf(b00, dx, fmaf(b01, dy, b02 * dz));                 \
                o1.L = fmaf(b10, dx, fmaf(b11, dy, b12 * dz));                 \
                o2.L = fmaf(b20, dx, fmaf(b21, dy, b22 * dz));                 \
            }
        LANE(v0a, v1a, v2a, o0a, o1a, o2a, x)
        LANE(v0a, v1a, v2a, o0a, o1a, o2a, y)
        LANE(v0a, v1a, v2a, o0a, o1a, o2a, z)
        LANE(v0a, v1a, v2a, o0a, o1a, o2a, w)
        LANE(v0b, v1b, v2b, o0b, o1b, o2b, x)
        LANE(v0b, v1b, v2b, o0b, o1b, o2b, y)
        LANE(v0b, v1b, v2b, o0b, o1b, o2b, z)
        LANE(v0b, v1b, v2b, o0b, o1b, o2b, w)
        #undef LANE

        O0[i0] = o0a; O1[i0] = o1a; O2[i0] = o2a;
        O3[i0] = a0a; O4[i0] = a1a; O5[i0] = a2a;
        if (p1) {
            O0[i1] = o0b; O1[i1] = o1b; O2[i1] = o2b;
            O3[i1] = a0b; O4[i1] = a1b; O5[i1] = a2b;
        }
    }
}

extern "C" void kernel_launch(void* const* d_in, const int* in_sizes, int n_in,
                              void* d_out, int out_size) {
    // Defensive: identify x (large) vs reference_axis (3 elements)
    int xi = 0, ri = 1;
    if (n_in >= 2 && in_sizes[0] == 3) { xi = 1; ri = 0; }
    const float* x  = (const float*)d_in[xi];
    const float* ra = (const float*)d_in[ri];
    const int T = in_sizes[xi] / 10;

    stats_kernel<<<NB_STATS, NT_STATS>>>(x, T);
    finalize_kernel<<<1, NB_STATS>>>(x, ra, T);

    const int T4 = T >> 2;
    // 2 grid-stride steps per thread: stride covers half of T4.
    int blocks = (T4 + 2 * 256 - 1) / (2 * 256);
    if (blocks < 1) blocks = 1;
    transform_kernel<<<blocks, 256>>>(x, (float*)d_out, T);
}

// round 12
// speedup vs baseline: 1.3466x; 1.3197x over previous
#include <cuda_runtime.h>
#include <math.h>

// ---------------------------------------------------------------------------
// TSControllerCoordinateTransform
//   x: (1, 10, T) f32, T = 4,000,000 ; reference_axis: (3,) f32
//   out: (2, 3, T) f32  = [new_basis @ (Xpos - refPos) ; Add]
//
// R8-R11 (2 kernels, clamp-indexed batched loads — fast path always active):
//   K1 stats_copy: 9 moments of rows 0..2 (asm-volatile LDG.128, MLP=12)
//                  + fused copy rows 7..9 -> out rows 3..5 (.cs streams)
//                  + last-block finalize (threadfence reduction -> params)
//   K2 transform:  newX = B*(Xpos-ref) for rows 0..2 -> out rows 0..2
// ---------------------------------------------------------------------------

#define NT 256
#define G1MAX 2048

__device__ double g_partials[G1MAX * 9];
__device__ float  g_params[12];        // basis row-major (9) + refPos (3)
__device__ unsigned int g_done = 0;    // reset by last block each run

// ---- asm load/store wrappers: volatile => ptxas cannot sink/reorder ----
__device__ __forceinline__ float4 ldg_v4(const float4* p) {
    float4 v;
    asm volatile("ld.global.v4.f32 {%0,%1,%2,%3}, [%4];"
                 : "=f"(v.x), "=f"(v.y), "=f"(v.z), "=f"(v.w) : "l"(p));
    return v;
}
__device__ __forceinline__ float4 ldg_v4_cs(const float4* p) {
    float4 v;
    asm volatile("ld.global.cs.v4.f32 {%0,%1,%2,%3}, [%4];"
                 : "=f"(v.x), "=f"(v.y), "=f"(v.z), "=f"(v.w) : "l"(p));
    return v;
}
__device__ __forceinline__ void stg_v4_cs(float4* p, float4 v) {
    asm volatile("st.global.cs.v4.f32 [%0], {%1,%2,%3,%4};"
                 :: "l"(p), "f"(v.x), "f"(v.y), "f"(v.z), "f"(v.w));
}

__inline__ __device__ double warp_reduce_d(double v) {
    #pragma unroll
    for (int o = 16; o > 0; o >>= 1)
        v += __shfl_down_sync(0xffffffffu, v, o);
    return v;
}

// ---- scalar finalize: cov -> f32 round -> f64 eigensolve -> basis ----
__device__ void compute_params(const float* __restrict__ x,
                               const float* __restrict__ ref_axis,
                               int T, const double* S) {
    const double n = (double)T;
    const double inv = 1.0 / (n - 1.0);
    const double mx = S[0] / n, my = S[1] / n, mz = S[2] / n;
    // Round cov to f32 — jnp's eigh input is the f32 cov matrix.
    double c00 = (double)(float)((S[3] - S[0] * mx) * inv);
    double c01 = (double)(float)((S[4] - S[0] * my) * inv);
    double c02 = (double)(float)((S[5] - S[0] * mz) * inv);
    double c11 = (double)(float)((S[6] - S[1] * my) * inv);
    double c12 = (double)(float)((S[7] - S[1] * mz) * inv);
    double c22 = (double)(float)((S[8] - S[2] * mz) * inv);

    double vx, vy, vz;
    const double p1 = c01 * c01 + c02 * c02 + c12 * c12;
    if (p1 < 1e-300) {
        vx = 1.0; vy = 0.0; vz = 0.0;
        if (c11 >= c00 && c11 >= c22) { vx = 0.0; vy = 1.0; }
        else if (c22 >= c00 && c22 >= c11) { vx = 0.0; vz = 1.0; }
    } else {
        const double q = (c00 + c11 + c22) / 3.0;
        const double p2 = (c00 - q) * (c00 - q) + (c11 - q) * (c11 - q) +
                          (c22 - q) * (c22 - q) + 2.0 * p1;
        const double p = sqrt(p2 / 6.0);
        const double ip = 1.0 / p;
        const double b00 = (c00 - q) * ip, b11 = (c11 - q) * ip, b22 = (c22 - q) * ip;
        const double b01 = c01 * ip, b02 = c02 * ip, b12 = c12 * ip;
        double r = 0.5 * (b00 * (b11 * b22 - b12 * b12)
                        - b01 * (b01 * b22 - b12 * b02)
                        + b02 * (b01 * b12 - b11 * b02));
        r = fmin(1.0, fmax(-1.0, r));
        const double phi = acos(r) / 3.0;
        const double lmax = q + 2.0 * p * cos(phi);

        const double m00 = c00 - lmax, m11 = c11 - lmax, m22 = c22 - lmax;
        double u0x = c01 * c12 - c02 * m11;   // r0 x r1
        double u0y = c02 * c01 - m00 * c12;
        double u0z = m00 * m11 - c01 * c01;
        double u1x = c01 * m22 - c02 * c12;   // r0 x r2
        double u1y = c02 * c02 - m00 * m22;
        double u1z = m00 * c12 - c01 * c02;
        double u2x = m11 * m22 - c12 * c12;   // r1 x r2
        double u2y = c12 * c02 - c01 * m22;
        double u2z = c01 * c12 - m11 * c02;
        double n0 = u0x * u0x + u0y * u0y + u0z * u0z;
        double n1 = u1x * u1x + u1y * u1y + u1z * u1z;
        double n2 = u2x * u2x + u2y * u2y + u2z * u2z;
        if (n0 >= n1 && n0 >= n2)      { vx = u0x; vy = u0y; vz = u0z; }
        else if (n1 >= n2)             { vx = u1x; vy = u1y; vz = u1z; }
        else                           { vx = u2x; vy = u2y; vz = u2z; }
        const double nrm = rsqrt(vx * vx + vy * vy + vz * vz);
        vx *= nrm; vy *= nrm; vz *= nrm;
    }

    // sign fix vs quaternion Z-forward (quat unnormalized, as in ref)
    const double qx = (double)x[3 * (size_t)T];
    const double qy = (double)x[4 * (size_t)T];
    const double qz = (double)x[5 * (size_t)T];
    const double qw = (double)x[6 * (size_t)T];
    const double zfx = 2.0 * (qx * qz + qw * qy);
    const double zfy = 2.0 * (qy * qz - qw * qx);
    const double zfz = 1.0 - 2.0 * (qx * qx + qy * qy);
    if (zfx * vx + zfy * vy + zfz * vz < 0.0) { vx = -vx; vy = -vy; vz = -vz; }

    // basis in f32 (matching jnp's f32 crosses)
    const float pzx = (float)vx, pzy = (float)vy, pzz = (float)vz;
    const float ax = ref_axis[0], ay = ref_axis[1], az = ref_axis[2];
    const float nrx = ay * pzz - az * pzy;    // new_right = cross(ref, pz)
    const float nry = az * pzx - ax * pzz;
    const float nrz = ax * pzy - ay * pzx;
    const float nfx = nry * az - nrz * ay;    // new_fwd = cross(new_right, new_up)
    const float nfy = nrz * ax - nrx * az;
    const float nfz = nrx * ay - nry * ax;

    g_params[0] = nrx; g_params[1] = nry; g_params[2] = nrz;
    g_params[3] = ax;  g_params[4] = ay;  g_params[5] = az;
    g_params[6] = nfx; g_params[7] = nfy; g_params[8] = nfz;
    g_params[9]  = x[0];
    g_params[10] = x[(size_t)T];
    g_params[11] = x[2 * (size_t)T];
}

#define ACC(AX, BX, CX)                                              \
    sx += (AX); sy += (BX); sz += (CX);                              \
    sxx = fmaf((AX), (AX), sxx); sxy = fmaf((AX), (BX), sxy);        \
    sxz = fmaf((AX), (CX), sxz); syy = fmaf((BX), (BX), syy);        \
    syz = fmaf((BX), (CX), syz); szz = fmaf((CX), (CX), szz);
#define ACC4S(A, B, C, M)                                            \
    ACC(A.x * M, B.x * M, C.x * M) ACC(A.y * M, B.y * M, C.y * M)    \
    ACC(A.z * M, B.z * M, C.z * M) ACC(A.w * M, B.w * M, C.w * M)

__global__ __launch_bounds__(NT)
void stats_copy_kernel(const float* __restrict__ x,
                       const float* __restrict__ ref_axis,
                       float* __restrict__ out, int T) {
    const int T4 = T >> 2;
    const int S = gridDim.x * NT;
    const int tid = blockIdx.x * NT + threadIdx.x;
    const int last = T4 - 1;

    const float4* __restrict__ r0 = reinterpret_cast<const float4*>(x);
    const float4* __restrict__ r1 = reinterpret_cast<const float4*>(x + T);
    const float4* __restrict__ r2 = reinterpret_cast<const float4*>(x + 2 * T);
    const float4* __restrict__ A0 = reinterpret_cast<const float4*>(x + 7 * (size_t)T);
    const float4* __restrict__ A1 = reinterpret_cast<const float4*>(x + 8 * (size_t)T);
    const float4* __restrict__ A2 = reinterpret_cast<const float4*>(x + 9 * (size_t)T);
    float4* __restrict__ O3 = reinterpret_cast<float4*>(out + 3 * (size_t)T);
    float4* __restrict__ O4 = reinterpret_cast<float4*>(out + 4 * (size_t)T);
    float4* __restrict__ O5 = reinterpret_cast<float4*>(out + 5 * (size_t)T);

    float sx = 0.f, sy = 0.f, sz = 0.f;
    float sxx = 0.f, sxy = 0.f, sxz = 0.f, syy = 0.f, syz = 0.f, szz = 0.f;

    // Each outer iteration handles 4 strided indices; clamp keeps every
    // address valid so the batched volatile loads need no predication.
    // Out-of-range stats contributions are zero-weighted (m in {0,1});
    // out-of-range copies write the clamped element's own correct value
    // (idempotent, race-safe).
    for (int i0 = tid; i0 < T4; i0 += 4 * S) {
        // ---- pair {i0, i0+S} : 12 back-to-back LDG.128 ----
        {
            const int j1 = i0 + S;
            const bool v1 = j1 < T4;
            const int k1 = v1 ? j1 : last;
            const float m1 = v1 ? 1.f : 0.f;
            float4 a0 = ldg_v4(r0 + i0), b0 = ldg_v4(r1 + i0), c0 = ldg_v4(r2 + i0);
            float4 a1 = ldg_v4(r0 + k1), b1 = ldg_v4(r1 + k1), c1 = ldg_v4(r2 + k1);
            float4 p0 = ldg_v4_cs(A0 + i0), q0 = ldg_v4_cs(A1 + i0), w0 = ldg_v4_cs(A2 + i0);
            float4 p1 = ldg_v4_cs(A0 + k1), q1 = ldg_v4_cs(A1 + k1), w1 = ldg_v4_cs(A2 + k1);
            stg_v4_cs(O3 + i0, p0); stg_v4_cs(O4 + i0, q0); stg_v4_cs(O5 + i0, w0);
            stg_v4_cs(O3 + k1, p1); stg_v4_cs(O4 + k1, q1); stg_v4_cs(O5 + k1, w1);
            ACC4S(a0, b0, c0, 1.f) ACC4S(a1, b1, c1, m1)
        }
        // ---- pair {i0+2S, i0+3S} ----
        {
            const int j2 = i0 + 2 * S, j3 = i0 + 3 * S;
            const bool v2 = j2 < T4, v3 = j3 < T4;
            const int k2 = v2 ? j2 : last, k3 = v3 ? j3 : last;
            const float m2 = v2 ? 1.f : 0.f, m3 = v3 ? 1.f : 0.f;
            float4 a0 = ldg_v4(r0 + k2), b0 = ldg_v4(r1 + k2), c0 = ldg_v4(r2 + k2);
            float4 a1 = ldg_v4(r0 + k3), b1 = ldg_v4(r1 + k3), c1 = ldg_v4(r2 + k3);
            float4 p0 = ldg_v4_cs(A0 + k2), q0 = ldg_v4_cs(A1 + k2), w0 = ldg_v4_cs(A2 + k2);
            float4 p1 = ldg_v4_cs(A0 + k3), q1 = ldg_v4_cs(A1 + k3), w1 = ldg_v4_cs(A2 + k3);
            stg_v4_cs(O3 + k2, p0); stg_v4_cs(O4 + k2, q0); stg_v4_cs(O5 + k2, w0);
            stg_v4_cs(O3 + k3, p1); stg_v4_cs(O4 + k3, q1); stg_v4_cs(O5 + k3, w1);
            ACC4S(a0, b0, c0, m2) ACC4S(a1, b1, c1, m3)
        }
    }

    // ---- block reduce (f64) ----
    double d[9] = {(double)sx, (double)sy, (double)sz,
                   (double)sxx, (double)sxy, (double)sxz,
                   (double)syy, (double)syz, (double)szz};
    __shared__ double s[(NT / 32) * 9];
    __shared__ bool is_last;
    const int lane = threadIdx.x & 31, warp = threadIdx.x >> 5;
    #pragma unroll
    for (int q = 0; q < 9; q++) {
        double v = warp_reduce_d(d[q]);
        if (lane == 0) s[warp * 9 + q] = v;
    }
    __syncthreads();
    if (threadIdx.x < 9) {
        double t = 0.0;
        #pragma unroll
        for (int w = 0; w < NT / 32; w++) t += s[w * 9 + threadIdx.x];
        g_partials[blockIdx.x * 9 + threadIdx.x] = t;
    }
    __threadfence();   // release: partials visible device-wide
    __syncthreads();
    if (threadIdx.x == 0)
        is_last = (atomicAdd(&g_done, 1u) == (unsigned)gridDim.x - 1u);
    __syncthreads();
    if (!is_last) return;

    // ---- last block: cross-block reduce + finalize ----
    __threadfence();  // acquire side
    double loc[9] = {0, 0, 0, 0, 0, 0, 0, 0, 0};
    for (int b = threadIdx.x; b < (int)gridDim.x; b += NT) {
        #pragma unroll
        for (int q = 0; q < 9; q++) loc[q] += __ldcg(&g_partials[b * 9 + q]);
    }
    __syncthreads();  // s[] reuse barrier
    #pragma unroll
    for (int q = 0; q < 9; q++) {
        double v = warp_reduce_d(loc[q]);
        if (lane == 0) s[warp * 9 + q] = v;
    }
    __syncthreads();
    if (threadIdx.x == 0) {
        double Sm[9];
        #pragma unroll
        for (int q = 0; q < 9; q++) {
            double t = 0.0;
            for (int w = 0; w < NT / 32; w++) t += s[w * 9 + q];
            Sm[q] = t;
        }
        compute_params(x, ref_axis, T, Sm);
        atomicExch(&g_done, 0u);   // reset for next graph replay
    }
}

__global__ __launch_bounds__(NT)
void transform_kernel(const float* __restrict__ x, float* __restrict__ out, int T) {
    const int T4 = T >> 2;
    const int S2 = gridDim.x * NT;
    const int tid = blockIdx.x * NT + threadIdx.x;
    const int last = T4 - 1;

    const float b00 = g_params[0], b01 = g_params[1], b02 = g_params[2];
    const float b10 = g_params[3], b11 = g_params[4], b12 = g_params[5];
    const float b20 = g_params[6], b21 = g_params[7], b22 = g_params[8];
    const float rx  = g_params[9], ry  = g_params[10], rz = g_params[11];

    const float4* __restrict__ X0 = reinterpret_cast<const float4*>(x);
    const float4* __restrict__ X1 = reinterpret_cast<const float4*>(x + T);
    const float4* __restrict__ X2 = reinterpret_cast<const float4*>(x + 2 * T);
    float4* __restrict__ O0 = reinterpret_cast<float4*>(out);
    float4* __restrict__ O1 = reinterpret_cast<float4*>(out + T);
    float4* __restrict__ O2 = reinterpret_cast<float4*>(out + 2 * T);

    #define XFRM(V0, V1, V2, P0, P1, P2, L)                                \
        {                                                                  \
            const float dx = V0.L - rx, dy = V1.L - ry, dz = V2.L - rz;    \
            P0.L = fmaf(b00, dx, fmaf(b01, dy, b02 * dz));                 \
            P1.L = fmaf(b10, dx, fmaf(b11, dy, b12 * dz));                 \
            P2.L = fmaf(b20, dx, fmaf(b21, dy, b22 * dz));                 \
        }

    for (int i0 = tid; i0 < T4; i0 += 2 * S2) {
        const int j1 = i0 + S2;
        const int k1 = (j1 < T4) ? j1 : last;   // idempotent clamp

        float4 v0a = ldg_v4(X0 + i0), v1a = ldg_v4(X1 + i0), v2a = ldg_v4(X2 + i0);
        float4 v0b = ldg_v4(X0 + k1), v1b = ldg_v4(X1 + k1), v2b = ldg_v4(X2 + k1);
        float4 o0a, o1a, o2a, o0b, o1b, o2b;
        XFRM(v0a, v1a, v2a, o0a, o1a, o2a, x)
        XFRM(v0a, v1a, v2a, o0a, o1a, o2a, y)
        XFRM(v0a, v1a, v2a, o0a, o1a, o2a, z)
        XFRM(v0a, v1a, v2a, o0a, o1a, o2a, w)
        XFRM(v0b, v1b, v2b, o0b, o1b, o2b, x)
        XFRM(v0b, v1b, v2b, o0b, o1b, o2b, y)
        XFRM(v0b, v1b, v2b, o0b, o1b, o2b, z)
        XFRM(v0b, v1b, v2b, o0b, o1b, o2b, w)
        stg_v4_cs(O0 + i0, o0a); stg_v4_cs(O1 + i0, o1a); stg_v4_cs(O2 + i0, o2a);
        stg_v4_cs(O0 + k1, o0b); stg_v4_cs(O1 + k1, o1b); stg_v4_cs(O2 + k1, o2b);
    }
    #undef XFRM
}

extern "C" void kernel_launch(void* const* d_in, const int* in_sizes, int n_in,
                              void* d_out, int out_size) {
    // Defensive: identify x (large) vs reference_axis (3 elements)
    int xi = 0, ri = 1;
    if (n_in >= 2 && in_sizes[0] == 3) { xi = 1; ri = 0; }
    const float* x  = (const float*)d_in[xi];
    const float* ra = (const float*)d_in[ri];
    const int T = in_sizes[xi] / 10;

    const int T4 = T >> 2;
    int g1 = (T4 + 4 * NT - 1) / (4 * NT);   // 4 indices per thread
    if (g1 < 1) g1 = 1;
    if (g1 > G1MAX) g1 = G1MAX;              // loop handles the rest
    stats_copy_kernel<<<g1, NT>>>(x, ra, (float*)d_out, T);

    int g2 = (T4 + 2 * NT - 1) / (2 * NT);   // 2 indices per thread
    if (g2 < 1) g2 = 1;
    transform_kernel<<<g2, NT>>>(x, (float*)d_out, T);
}